// round 4
// baseline (speedup 1.0000x reference)
#include <cuda_runtime.h>

// R2D2Head: B tasks, s=25 support, d=640, 5-way, q=75 queries
#define NS 25
#define DQ 640
#define NWAY 5
#define NQ 75
#define RIDGE 50.0f

#define SR 644     // S smem row stride: multiple of 4 (float4), conflict-free
#define ACOLS 32   // augmented matrix row stride
#define WS 656     // W_T row stride (multiple of 4)

// shared memory layout (in floats)
#define OFF_S    0                        // 25*644 = 16100
#define OFF_A    16100                    // 25*32  = 800
#define OFF_SOL  16900                    // 25*8   = 200
#define OFF_WT   17100                    // 5*656  = 3280
#define OFF_LOG  20380                    // 376
#define OFF_FLAG 20756                    // 4
#define SMEM_FLOATS 20760                 // 83040 bytes

__global__ __launch_bounds__(256, 2)
void r2d2_kernel(const float* __restrict__ query,
                 const float* __restrict__ support,
                 const int* __restrict__ labels_raw,
                 float* __restrict__ out)
{
    extern __shared__ float sm[];
    float* Ssm = sm + OFF_S;
    float* A   = sm + OFF_A;
    float* SOL = sm + OFF_SOL;
    float* WT  = sm + OFF_WT;
    float* LOG = sm + OFF_LOG;
    int*  FLAG = (int*)(sm + OFF_FLAG);

    const int b = blockIdx.x;
    const int t = threadIdx.x;
    const int warp = t >> 5, lane = t & 31;

    // ---- Phase 0: label dtype sniff (int64 vs int32), deterministic ----
    // Labels in [0,4]. int64 viewed as int32 words = {val,0,val,0,...}.
    // Genuine int32 data: P(64 consecutive odd words all zero) = 5^-64 ~ 0.
    if (t == 0) {
        int i64 = 1;
        #pragma unroll 1
        for (int i = 0; i < 128; i += 2) {
            int lo = labels_raw[i], hi = labels_raw[i + 1];
            if (hi != 0 || lo < 0 || lo > 4) { i64 = 0; break; }
        }
        FLAG[0] = i64;
    }

    // ---- Phase 1: load S (25 x 640) into smem, row stride 644 ----
    const float* Sg = support + (size_t)b * NS * DQ;
    for (int idx = t; idx < NS * DQ; idx += 256) {
        int row = idx / DQ;
        int col = idx - row * DQ;
        Ssm[row * SR + col] = Sg[idx];
    }
    __syncthreads();

    const int lab_i64 = FLAG[0];

    // ---- Phase 2: gram, warp-collective dots over triangular pairs ----
    for (int p = warp; p < 325; p += 8) {
        int i = 0, rem = p;
        while (rem >= NS - i) { rem -= NS - i; ++i; }
        int j = i + rem;

        float part = 0.f;
        #pragma unroll
        for (int k = 0; k < 5; ++k) {
            int d4 = lane + k * 32;                 // float4 index 0..159
            float4 av = *(const float4*)&Ssm[i * SR + 4 * d4];
            float4 bv = *(const float4*)&Ssm[j * SR + 4 * d4];
            part = fmaf(av.x, bv.x, part);
            part = fmaf(av.y, bv.y, part);
            part = fmaf(av.z, bv.z, part);
            part = fmaf(av.w, bv.w, part);
        }
        #pragma unroll
        for (int off = 16; off > 0; off >>= 1)
            part += __shfl_xor_sync(0xffffffffu, part, off);

        if (lane == 0) {
            float v = part + (i == j ? RIDGE : 0.f);
            A[i * ACOLS + j] = v;
            A[j * ACOLS + i] = v;
        }
    }
    // one-hot Y into columns 25..29
    if (t < 125) {
        int i = t / 5, w = t - i * 5;
        int base = b * NS + i;
        int lab = lab_i64 ? labels_raw[2 * base] : labels_raw[base];
        A[i * ACOLS + 25 + w] = (lab == w) ? 1.f : 0.f;
    }
    __syncthreads();

    // ---- Phase 3: solve, single-warp Gauss-Jordan (SPD + ridge) ----
    if (warp == 0) {
        for (int k = 0; k < NS; ++k) {
            float f = 0.f;
            bool act = (lane < NS) && (lane != k);
            if (act) f = A[lane * ACOLS + k] / A[k * ACOLS + k];
            __syncwarp();
            if (act) {
                for (int j = k; j < 30; ++j)
                    A[lane * ACOLS + j] -= f * A[k * ACOLS + j];
            }
            __syncwarp();
        }
    }
    __syncthreads();
    if (t < 125) {
        int i = t / 5, w = t - i * 5;
        SOL[i * 8 + w] = A[i * ACOLS + 25 + w] / A[i * ACOLS + i];
    }
    __syncthreads();

    // ---- Phase 4: W_T[w][d] = sum_s S[s][d] * sol[s][w] ----
    {
        int d0 = t;
        int d1 = t + 256;
        int d2 = t + 512;
        bool h2 = (d2 < DQ);      // t < 128
        float a0[5], a1[5], a2[5];
        #pragma unroll
        for (int w = 0; w < 5; ++w) { a0[w] = 0.f; a1[w] = 0.f; a2[w] = 0.f; }
        for (int s = 0; s < NS; ++s) {
            float s0 = Ssm[s * SR + d0];
            float s1 = Ssm[s * SR + d1];
            float s2 = h2 ? Ssm[s * SR + d2] : 0.f;
            #pragma unroll
            for (int w = 0; w < 5; ++w) {
                float sv = SOL[s * 8 + w];
                a0[w] = fmaf(s0, sv, a0[w]);
                a1[w] = fmaf(s1, sv, a1[w]);
                a2[w] = fmaf(s2, sv, a2[w]);
            }
        }
        #pragma unroll
        for (int w = 0; w < 5; ++w) {
            WT[w * WS + d0] = a0[w];
            WT[w * WS + d1] = a1[w];
            if (h2) WT[w * WS + d2] = a2[w];
        }
    }
    __syncthreads();

    // ---- Phase 5: logits = Q @ W, warp per 5 query rows, float4 streams ----
    {
        const float4* Qb = (const float4*)(query + (size_t)b * NQ * DQ);
        for (int g = warp; g < 15; g += 8) {
            int r0 = g * 5;
            float acc[5][5];
            #pragma unroll
            for (int r = 0; r < 5; ++r)
                #pragma unroll
                for (int w = 0; w < 5; ++w) acc[r][w] = 0.f;

            #pragma unroll
            for (int it = 0; it < 5; ++it) {
                int d4 = lane + it * 32;          // float4 index, 0..159
                float4 qv[5], wv[5];
                #pragma unroll
                for (int r = 0; r < 5; ++r) qv[r] = Qb[(r0 + r) * 160 + d4];
                #pragma unroll
                for (int w = 0; w < 5; ++w)
                    wv[w] = *(const float4*)&WT[w * WS + d4 * 4];
                #pragma unroll
                for (int r = 0; r < 5; ++r)
                    #pragma unroll
                    for (int w = 0; w < 5; ++w) {
                        acc[r][w] = fmaf(qv[r].x, wv[w].x, acc[r][w]);
                        acc[r][w] = fmaf(qv[r].y, wv[w].y, acc[r][w]);
                        acc[r][w] = fmaf(qv[r].z, wv[w].z, acc[r][w]);
                        acc[r][w] = fmaf(qv[r].w, wv[w].w, acc[r][w]);
                    }
            }
            #pragma unroll
            for (int r = 0; r < 5; ++r)
                #pragma unroll
                for (int w = 0; w < 5; ++w) {
                    float v = acc[r][w];
                    v += __shfl_xor_sync(0xffffffffu, v, 16);
                    v += __shfl_xor_sync(0xffffffffu, v, 8);
                    v += __shfl_xor_sync(0xffffffffu, v, 4);
                    v += __shfl_xor_sync(0xffffffffu, v, 2);
                    v += __shfl_xor_sync(0xffffffffu, v, 1);
                    acc[r][w] = v;
                }
            if (lane == 0) {
                #pragma unroll
                for (int r = 0; r < 5; ++r)
                    #pragma unroll
                    for (int w = 0; w < 5; ++w)
                        LOG[(r0 + r) * 5 + w] = acc[r][w];
            }
        }
    }
    __syncthreads();

    // ---- Phase 6: coalesced output store (FIX: strided loop, 375 > 256) ----
    for (int idx = t; idx < NQ * NWAY; idx += 256)
        out[(size_t)b * (NQ * NWAY) + idx] = LOG[idx];
}

extern "C" void kernel_launch(void* const* d_in, const int* in_sizes, int n_in,
                              void* d_out, int out_size)
{
    const float* query   = (const float*)d_in[0];
    const float* support = (const float*)d_in[1];
    const int* labels    = (const int*)d_in[2];
    float* out = (float*)d_out;

    int tasks = in_sizes[1] / (NS * DQ);   // 2048

    size_t smem_bytes = (size_t)SMEM_FLOATS * sizeof(float);
    cudaFuncSetAttribute(r2d2_kernel,
                         cudaFuncAttributeMaxDynamicSharedMemorySize,
                         (int)smem_bytes);

    r2d2_kernel<<<tasks, 256, smem_bytes>>>(query, support, labels, out);
}

// round 5
// speedup vs baseline: 1.5245x; 1.5245x over previous
#include <cuda_runtime.h>

// R2D2Head: B tasks (2048), s=25 support, d=640, 5-way, q=75 queries
#define NS 25
#define DQ 640
#define NWAY 5
#define NQ 75
#define RIDGE 50.0f
#define TASKS_MAX 2048

#define SR 640     // S smem row stride (row-major consecutive access -> conflict-free)
#define ACOLS 32   // augmented matrix row stride
#define WS 640     // W_T smem row stride in kernel B

// 26.2 MB device scratch for W (allowed: static __device__ array)
__device__ float g_W[TASKS_MAX * NWAY * DQ];

// ---------------- Kernel A: gram + solve + W ----------------
// smem: S 16000 | A 800 | SOL 200 | FLAG 4  = 17004 floats (68 KB) -> 3 CTAs/SM
#define A_OFF_S    0
#define A_OFF_A    16000
#define A_OFF_SOL  16800
#define A_OFF_FLAG 17000
#define A_SMEM_FLOATS 17004

__global__ __launch_bounds__(256, 3)
void r2d2_prep(const float* __restrict__ support,
               const int* __restrict__ labels_raw)
{
    extern __shared__ float sm[];
    float* Ssm = sm + A_OFF_S;
    float* A   = sm + A_OFF_A;
    float* SOL = sm + A_OFF_SOL;
    int*  FLAG = (int*)(sm + A_OFF_FLAG);

    const int b = blockIdx.x;
    const int t = threadIdx.x;
    const int warp = t >> 5, lane = t & 31;

    // ---- label dtype sniff (int64 vs int32), deterministic ----
    if (t == 0) {
        int i64 = 1;
        #pragma unroll 1
        for (int i = 0; i < 128; i += 2) {
            int lo = labels_raw[i], hi = labels_raw[i + 1];
            if (hi != 0 || lo < 0 || lo > 4) { i64 = 0; break; }
        }
        FLAG[0] = i64;
    }

    // ---- load S (25 x 640) via float4, streaming hint ----
    const float4* Sg4 = (const float4*)(support + (size_t)b * NS * DQ);
    float4* Ss4 = (float4*)Ssm;
    for (int idx = t; idx < NS * DQ / 4; idx += 256)
        Ss4[idx] = __ldcs(&Sg4[idx]);   // SR==DQ so layout is identical
    __syncthreads();

    const int lab_i64 = FLAG[0];

    // ---- gram: warp per 5x5 triangular tile (15 tiles), lanes split d ----
    for (int tile = warp; tile < 15; tile += 8) {
        int ti = 0, rem = tile;                 // decode ti<=tj
        while (rem >= 5 - ti) { rem -= 5 - ti; ++ti; }
        int tj = ti + rem;

        float acc[5][5];
        #pragma unroll
        for (int r = 0; r < 5; ++r)
            #pragma unroll
            for (int c = 0; c < 5; ++c) acc[r][c] = 0.f;

        const float* Ri = Ssm + (5 * ti) * SR;
        const float* Rj = Ssm + (5 * tj) * SR;
        for (int it = 0; it < 20; ++it) {       // 20*32 = 640
            int d = lane + it * 32;
            float av[5], bv[5];
            #pragma unroll
            for (int r = 0; r < 5; ++r) av[r] = Ri[r * SR + d];
            #pragma unroll
            for (int c = 0; c < 5; ++c) bv[c] = Rj[c * SR + d];
            #pragma unroll
            for (int r = 0; r < 5; ++r)
                #pragma unroll
                for (int c = 0; c < 5; ++c)
                    acc[r][c] = fmaf(av[r], bv[c], acc[r][c]);
        }
        // reduce each acc to lane 0
        #pragma unroll
        for (int r = 0; r < 5; ++r)
            #pragma unroll
            for (int c = 0; c < 5; ++c) {
                float v = acc[r][c];
                v += __shfl_down_sync(0xffffffffu, v, 16);
                v += __shfl_down_sync(0xffffffffu, v, 8);
                v += __shfl_down_sync(0xffffffffu, v, 4);
                v += __shfl_down_sync(0xffffffffu, v, 2);
                v += __shfl_down_sync(0xffffffffu, v, 1);
                acc[r][c] = v;
            }
        if (lane == 0) {
            #pragma unroll
            for (int r = 0; r < 5; ++r)
                #pragma unroll
                for (int c = 0; c < 5; ++c) {
                    int i = 5 * ti + r, j = 5 * tj + c;
                    float v = acc[r][c] + (i == j ? RIDGE : 0.f);
                    A[i * ACOLS + j] = v;
                    A[j * ACOLS + i] = v;
                }
        }
    }
    // one-hot Y into columns 25..29
    if (t < 125) {
        int i = t / 5, w = t - i * 5;
        int base = b * NS + i;
        int lab = lab_i64 ? labels_raw[2 * base] : labels_raw[base];
        A[i * ACOLS + 25 + w] = (lab == w) ? 1.f : 0.f;
    }
    __syncthreads();

    // ---- solve: single-warp Gauss-Jordan (SPD + ridge, no pivoting) ----
    if (warp == 0) {
        for (int k = 0; k < NS; ++k) {
            float f = 0.f;
            bool act = (lane < NS) && (lane != k);
            if (act) f = A[lane * ACOLS + k] / A[k * ACOLS + k];
            __syncwarp();
            if (act) {
                for (int j = k; j < 30; ++j)
                    A[lane * ACOLS + j] -= f * A[k * ACOLS + j];
            }
            __syncwarp();
        }
    }
    __syncthreads();
    if (t < 125) {
        int i = t / 5, w = t - i * 5;
        SOL[i * 8 + w] = A[i * ACOLS + 25 + w] / A[i * ACOLS + i];
    }
    __syncthreads();

    // ---- W[w][d] = sum_s S[s][d] * sol[s][w]  -> global scratch ----
    {
        float* Wb = g_W + (size_t)b * NWAY * DQ;
        int d0 = t, d1 = t + 256, d2 = t + 512;
        bool h2 = (d2 < DQ);
        float a0[5], a1[5], a2[5];
        #pragma unroll
        for (int w = 0; w < 5; ++w) { a0[w] = 0.f; a1[w] = 0.f; a2[w] = 0.f; }
        for (int s = 0; s < NS; ++s) {
            float s0 = Ssm[s * SR + d0];
            float s1 = Ssm[s * SR + d1];
            float s2 = h2 ? Ssm[s * SR + d2] : 0.f;
            #pragma unroll
            for (int w = 0; w < 5; ++w) {
                float sv = SOL[s * 8 + w];
                a0[w] = fmaf(s0, sv, a0[w]);
                a1[w] = fmaf(s1, sv, a1[w]);
                a2[w] = fmaf(s2, sv, a2[w]);
            }
        }
        #pragma unroll
        for (int w = 0; w < 5; ++w) {
            Wb[w * DQ + d0] = a0[w];
            Wb[w * DQ + d1] = a1[w];
            if (h2) Wb[w * DQ + d2] = a2[w];
        }
    }
}

// ---------------- Kernel B: logits = Q @ W ----------------
// smem: WT 3200 | LOG 376 = 3576 floats (14.3 KB) -> occupancy reg-limited
#define B_OFF_WT  0
#define B_OFF_LOG 3200
#define B_SMEM_FLOATS 3576

__global__ __launch_bounds__(256, 3)
void r2d2_logits(const float* __restrict__ query,
                 float* __restrict__ out)
{
    extern __shared__ float sm[];
    float* WT  = sm + B_OFF_WT;
    float* LOG = sm + B_OFF_LOG;

    const int b = blockIdx.x;
    const int t = threadIdx.x;
    const int warp = t >> 5, lane = t & 31;

    // load W tile (5 x 640) to smem via float4
    {
        const float4* Wg4 = (const float4*)(g_W + (size_t)b * NWAY * DQ);
        float4* Wt4 = (float4*)WT;
        for (int idx = t; idx < NWAY * DQ / 4; idx += 256)
            Wt4[idx] = Wg4[idx];
    }
    __syncthreads();

    // warp per 5 query rows; 15 groups over 8 warps
    const float4* Qb = (const float4*)(query + (size_t)b * NQ * DQ);
    for (int g = warp; g < 15; g += 8) {
        int r0 = g * 5;
        float acc[5][5];
        #pragma unroll
        for (int r = 0; r < 5; ++r)
            #pragma unroll
            for (int w = 0; w < 5; ++w) acc[r][w] = 0.f;

        #pragma unroll
        for (int it = 0; it < 5; ++it) {
            int d4 = lane + it * 32;              // float4 index 0..159
            float4 qv[5], wv[5];
            #pragma unroll
            for (int r = 0; r < 5; ++r) qv[r] = __ldcs(&Qb[(r0 + r) * 160 + d4]);
            #pragma unroll
            for (int w = 0; w < 5; ++w)
                wv[w] = *(const float4*)&WT[w * WS + d4 * 4];
            #pragma unroll
            for (int r = 0; r < 5; ++r)
                #pragma unroll
                for (int w = 0; w < 5; ++w) {
                    acc[r][w] = fmaf(qv[r].x, wv[w].x, acc[r][w]);
                    acc[r][w] = fmaf(qv[r].y, wv[w].y, acc[r][w]);
                    acc[r][w] = fmaf(qv[r].z, wv[w].z, acc[r][w]);
                    acc[r][w] = fmaf(qv[r].w, wv[w].w, acc[r][w]);
                }
        }
        #pragma unroll
        for (int r = 0; r < 5; ++r)
            #pragma unroll
            for (int w = 0; w < 5; ++w) {
                float v = acc[r][w];
                v += __shfl_xor_sync(0xffffffffu, v, 16);
                v += __shfl_xor_sync(0xffffffffu, v, 8);
                v += __shfl_xor_sync(0xffffffffu, v, 4);
                v += __shfl_xor_sync(0xffffffffu, v, 2);
                v += __shfl_xor_sync(0xffffffffu, v, 1);
                acc[r][w] = v;
            }
        if (lane == 0) {
            #pragma unroll
            for (int r = 0; r < 5; ++r)
                #pragma unroll
                for (int w = 0; w < 5; ++w)
                    LOG[(r0 + r) * 5 + w] = acc[r][w];
        }
    }
    __syncthreads();

    // coalesced output store (375 entries, strided)
    for (int idx = t; idx < NQ * NWAY; idx += 256)
        out[(size_t)b * (NQ * NWAY) + idx] = LOG[idx];
}

extern "C" void kernel_launch(void* const* d_in, const int* in_sizes, int n_in,
                              void* d_out, int out_size)
{
    const float* query   = (const float*)d_in[0];
    const float* support = (const float*)d_in[1];
    const int* labels    = (const int*)d_in[2];
    float* out = (float*)d_out;

    int tasks = in_sizes[1] / (NS * DQ);   // 2048
    if (tasks > TASKS_MAX) tasks = TASKS_MAX;

    size_t smemA = (size_t)A_SMEM_FLOATS * sizeof(float);
    cudaFuncSetAttribute(r2d2_prep,
                         cudaFuncAttributeMaxDynamicSharedMemorySize, (int)smemA);
    size_t smemB = (size_t)B_SMEM_FLOATS * sizeof(float);

    r2d2_prep<<<tasks, 256, smemA>>>(support, labels);
    r2d2_logits<<<tasks, 256, smemB>>>(query, out);
}

// round 6
// speedup vs baseline: 2.2496x; 1.4756x over previous
#include <cuda_runtime.h>

// R2D2Head: B tasks (2048), s=25 support, d=640, 5-way, q=75 queries
#define NS 25
#define DQ 640
#define NWAY 5
#define NQ 75
#define RIDGE 50.0f
#define TASKS_MAX 2048

#define SR 640     // S smem row stride
#define ACOLS 33   // augmented matrix row stride (33 -> conflict-free column access)
#define WS 640     // W_T smem row stride in kernel B

// 26.2 MB device scratch for W
__device__ float g_W[TASKS_MAX * NWAY * DQ];

// ---------------- Kernel A: gram + solve + W ----------------
// smem: S 16000 | A 25*33=825 | SOL 200 | FLAG 4 -> 17032 floats (68.1 KB), 3 CTAs/SM
#define A_OFF_S    0
#define A_OFF_A    16000
#define A_OFF_SOL  16828
#define A_OFF_FLAG 17028
#define A_SMEM_FLOATS 17032

__global__ __launch_bounds__(256, 3)
void r2d2_prep(const float* __restrict__ support,
               const int* __restrict__ labels_raw)
{
    extern __shared__ float sm[];
    float* Ssm = sm + A_OFF_S;
    float* A   = sm + A_OFF_A;
    float* SOL = sm + A_OFF_SOL;
    int*  FLAG = (int*)(sm + A_OFF_FLAG);

    const int b = blockIdx.x;
    const int t = threadIdx.x;
    const int warp = t >> 5, lane = t & 31;

    // ---- label dtype sniff: PARALLEL (one load latency, not 64 serial) ----
    // warp 0 lanes check 32 int32-pairs. int64 labels in [0,4] look like
    // {lo in [0,4], hi==0}. Genuine int32: P(all 32 pass) = 5^-32 ~ 4e-23.
    if (warp == 0) {
        int lo = labels_raw[2 * lane];
        int hi = labels_raw[2 * lane + 1];
        bool ok = (hi == 0) && (lo >= 0) && (lo <= 4);
        unsigned m = __ballot_sync(0xffffffffu, ok);
        if (lane == 0) FLAG[0] = (m == 0xffffffffu) ? 1 : 0;
    }

    // ---- load S (25 x 640) via float4, streaming hint ----
    const float4* Sg4 = (const float4*)(support + (size_t)b * NS * DQ);
    float4* Ss4 = (float4*)Ssm;
    for (int idx = t; idx < NS * DQ / 4; idx += 256)
        Ss4[idx] = __ldcs(&Sg4[idx]);
    __syncthreads();

    const int lab_i64 = FLAG[0];

    // ---- gram: warp per 5x5 triangular tile (15 tiles), lanes split d ----
    for (int tile = warp; tile < 15; tile += 8) {
        int ti = 0, rem = tile;
        while (rem >= 5 - ti) { rem -= 5 - ti; ++ti; }
        int tj = ti + rem;

        float acc[5][5];
        #pragma unroll
        for (int r = 0; r < 5; ++r)
            #pragma unroll
            for (int c = 0; c < 5; ++c) acc[r][c] = 0.f;

        const float* Ri = Ssm + (5 * ti) * SR;
        const float* Rj = Ssm + (5 * tj) * SR;
        for (int it = 0; it < 20; ++it) {
            int d = lane + it * 32;
            float av[5], bv[5];
            #pragma unroll
            for (int r = 0; r < 5; ++r) av[r] = Ri[r * SR + d];
            #pragma unroll
            for (int c = 0; c < 5; ++c) bv[c] = Rj[c * SR + d];
            #pragma unroll
            for (int r = 0; r < 5; ++r)
                #pragma unroll
                for (int c = 0; c < 5; ++c)
                    acc[r][c] = fmaf(av[r], bv[c], acc[r][c]);
        }
        #pragma unroll
        for (int r = 0; r < 5; ++r)
            #pragma unroll
            for (int c = 0; c < 5; ++c) {
                float v = acc[r][c];
                v += __shfl_down_sync(0xffffffffu, v, 16);
                v += __shfl_down_sync(0xffffffffu, v, 8);
                v += __shfl_down_sync(0xffffffffu, v, 4);
                v += __shfl_down_sync(0xffffffffu, v, 2);
                v += __shfl_down_sync(0xffffffffu, v, 1);
                acc[r][c] = v;
            }
        if (lane == 0) {
            #pragma unroll
            for (int r = 0; r < 5; ++r)
                #pragma unroll
                for (int c = 0; c < 5; ++c) {
                    int i = 5 * ti + r, j = 5 * tj + c;
                    float v = acc[r][c] + (i == j ? RIDGE : 0.f);
                    A[i * ACOLS + j] = v;
                    A[j * ACOLS + i] = v;
                }
        }
    }
    // one-hot Y into columns 25..29
    if (t < 125) {
        int i = t / 5, w = t - i * 5;
        int base = b * NS + i;
        int lab = lab_i64 ? labels_raw[2 * base] : labels_raw[base];
        A[i * ACOLS + 25 + w] = (lab == w) ? 1.f : 0.f;
    }
    __syncthreads();

    // ---- solve: single-warp Gauss-Jordan, now conflict-free (ACOLS=33) ----
    if (warp == 0) {
        for (int k = 0; k < NS; ++k) {
            float f = 0.f;
            bool act = (lane < NS) && (lane != k);
            if (act) f = A[lane * ACOLS + k] / A[k * ACOLS + k];
            __syncwarp();
            if (act) {
                for (int j = k; j < 30; ++j)
                    A[lane * ACOLS + j] -= f * A[k * ACOLS + j];
            }
            __syncwarp();
        }
    }
    __syncthreads();
    if (t < 125) {
        int i = t / 5, w = t - i * 5;
        SOL[i * 8 + w] = A[i * ACOLS + 25 + w] / A[i * ACOLS + i];
    }
    __syncthreads();

    // ---- W[w][d] = sum_s S[s][d] * sol[s][w]  -> global scratch ----
    {
        float* Wb = g_W + (size_t)b * NWAY * DQ;
        int d0 = t, d1 = t + 256, d2 = t + 512;
        bool h2 = (d2 < DQ);
        float a0[5], a1[5], a2[5];
        #pragma unroll
        for (int w = 0; w < 5; ++w) { a0[w] = 0.f; a1[w] = 0.f; a2[w] = 0.f; }
        for (int s = 0; s < NS; ++s) {
            float s0 = Ssm[s * SR + d0];
            float s1 = Ssm[s * SR + d1];
            float s2 = h2 ? Ssm[s * SR + d2] : 0.f;
            #pragma unroll
            for (int w = 0; w < 5; ++w) {
                float sv = SOL[s * 8 + w];
                a0[w] = fmaf(s0, sv, a0[w]);
                a1[w] = fmaf(s1, sv, a1[w]);
                a2[w] = fmaf(s2, sv, a2[w]);
            }
        }
        #pragma unroll
        for (int w = 0; w < 5; ++w) {
            Wb[w * DQ + d0] = a0[w];
            Wb[w * DQ + d1] = a1[w];
            if (h2) Wb[w * DQ + d2] = a2[w];
        }
    }
}

// ---------------- Kernel B: logits = Q @ W (unchanged: 70% DRAM SOL) ----------------
#define B_OFF_WT  0
#define B_OFF_LOG 3200
#define B_SMEM_FLOATS 3576

__global__ __launch_bounds__(256, 3)
void r2d2_logits(const float* __restrict__ query,
                 float* __restrict__ out)
{
    extern __shared__ float sm[];
    float* WT  = sm + B_OFF_WT;
    float* LOG = sm + B_OFF_LOG;

    const int b = blockIdx.x;
    const int t = threadIdx.x;
    const int warp = t >> 5, lane = t & 31;

    {
        const float4* Wg4 = (const float4*)(g_W + (size_t)b * NWAY * DQ);
        float4* Wt4 = (float4*)WT;
        for (int idx = t; idx < NWAY * DQ / 4; idx += 256)
            Wt4[idx] = Wg4[idx];
    }
    __syncthreads();

    const float4* Qb = (const float4*)(query + (size_t)b * NQ * DQ);
    for (int g = warp; g < 15; g += 8) {
        int r0 = g * 5;
        float acc[5][5];
        #pragma unroll
        for (int r = 0; r < 5; ++r)
            #pragma unroll
            for (int w = 0; w < 5; ++w) acc[r][w] = 0.f;

        #pragma unroll
        for (int it = 0; it < 5; ++it) {
            int d4 = lane + it * 32;
            float4 qv[5], wv[5];
            #pragma unroll
            for (int r = 0; r < 5; ++r) qv[r] = __ldcs(&Qb[(r0 + r) * 160 + d4]);
            #pragma unroll
            for (int w = 0; w < 5; ++w)
                wv[w] = *(const float4*)&WT[w * WS + d4 * 4];
            #pragma unroll
            for (int r = 0; r < 5; ++r)
                #pragma unroll
                for (int w = 0; w < 5; ++w) {
                    acc[r][w] = fmaf(qv[r].x, wv[w].x, acc[r][w]);
                    acc[r][w] = fmaf(qv[r].y, wv[w].y, acc[r][w]);
                    acc[r][w] = fmaf(qv[r].z, wv[w].z, acc[r][w]);
                    acc[r][w] = fmaf(qv[r].w, wv[w].w, acc[r][w]);
                }
        }
        #pragma unroll
        for (int r = 0; r < 5; ++r)
            #pragma unroll
            for (int w = 0; w < 5; ++w) {
                float v = acc[r][w];
                v += __shfl_xor_sync(0xffffffffu, v, 16);
                v += __shfl_xor_sync(0xffffffffu, v, 8);
                v += __shfl_xor_sync(0xffffffffu, v, 4);
                v += __shfl_xor_sync(0xffffffffu, v, 2);
                v += __shfl_xor_sync(0xffffffffu, v, 1);
                acc[r][w] = v;
            }
        if (lane == 0) {
            #pragma unroll
            for (int r = 0; r < 5; ++r)
                #pragma unroll
                for (int w = 0; w < 5; ++w)
                    LOG[(r0 + r) * 5 + w] = acc[r][w];
        }
    }
    __syncthreads();

    for (int idx = t; idx < NQ * NWAY; idx += 256)
        out[(size_t)b * (NQ * NWAY) + idx] = LOG[idx];
}

extern "C" void kernel_launch(void* const* d_in, const int* in_sizes, int n_in,
                              void* d_out, int out_size)
{
    const float* query   = (const float*)d_in[0];
    const float* support = (const float*)d_in[1];
    const int* labels    = (const int*)d_in[2];
    float* out = (float*)d_out;

    int tasks = in_sizes[1] / (NS * DQ);   // 2048
    if (tasks > TASKS_MAX) tasks = TASKS_MAX;

    size_t smemA = (size_t)A_SMEM_FLOATS * sizeof(float);
    cudaFuncSetAttribute(r2d2_prep,
                         cudaFuncAttributeMaxDynamicSharedMemorySize, (int)smemA);
    size_t smemB = (size_t)B_SMEM_FLOATS * sizeof(float);

    r2d2_prep<<<tasks, 256, smemA>>>(support, labels);
    r2d2_logits<<<tasks, 256, smemB>>>(query, out);
}

// round 7
// speedup vs baseline: 2.7335x; 1.2151x over previous
#include <cuda_runtime.h>

// R2D2Head: B tasks (2048), s=25 support, d=640, 5-way, q=75 queries
#define NS 25
#define DQ 640
#define NWAY 5
#define NQ 75
#define RIDGE 50.0f
#define TASKS_MAX 2048

#define SR 640     // S smem row stride
#define ACOLS 33   // augmented matrix row stride (conflict-free columns)
#define WS 640     // W_T smem row stride in kernel B

__device__ float g_W[TASKS_MAX * NWAY * DQ];   // 26.2 MB scratch

// packed fp32x2 FMA (FFMA2) — only reachable via PTX
__device__ __forceinline__ void fma_f32x2(unsigned long long& acc,
                                          unsigned long long a,
                                          unsigned long long b)
{
    asm("fma.rn.f32x2 %0, %1, %2, %0;" : "+l"(acc) : "l"(a), "l"(b));
}

// ---------------- Kernel A: gram + solve + W ----------------
// smem: S 16000 | A 25*33=825 | SOL 200 | FLAG 4 -> 17032 floats (68.1 KB), 3 CTAs/SM
#define A_OFF_S    0
#define A_OFF_A    16000
#define A_OFF_SOL  16828
#define A_OFF_FLAG 17028
#define A_SMEM_FLOATS 17032

__global__ __launch_bounds__(256, 3)
void r2d2_prep(const float* __restrict__ support,
               const int* __restrict__ labels_raw)
{
    extern __shared__ float sm[];
    float* Ssm = sm + A_OFF_S;
    float* A   = sm + A_OFF_A;
    float* SOL = sm + A_OFF_SOL;
    int*  FLAG = (int*)(sm + A_OFF_FLAG);

    const int b = blockIdx.x;
    const int t = threadIdx.x;
    const int warp = t >> 5, lane = t & 31;

    // ---- label dtype sniff: parallel, one load latency ----
    if (warp == 0) {
        int lo = labels_raw[2 * lane];
        int hi = labels_raw[2 * lane + 1];
        bool ok = (hi == 0) && (lo >= 0) && (lo <= 4);
        unsigned m = __ballot_sync(0xffffffffu, ok);
        if (lane == 0) FLAG[0] = (m == 0xffffffffu) ? 1 : 0;
    }

    // ---- load S (25 x 640) via float4, streaming hint ----
    const float4* Sg4 = (const float4*)(support + (size_t)b * NS * DQ);
    float4* Ss4 = (float4*)Ssm;
    for (int idx = t; idx < NS * DQ / 4; idx += 256)
        Ss4[idx] = __ldcs(&Sg4[idx]);
    __syncthreads();

    const int lab_i64 = FLAG[0];

    // ---- gram: warp per 5x5 triangular tile, packed f32x2 FMA ----
    for (int tile = warp; tile < 15; tile += 8) {
        int ti = 0, rem = tile;
        while (rem >= 5 - ti) { rem -= 5 - ti; ++ti; }
        int tj = ti + rem;

        unsigned long long acc2[5][5];
        #pragma unroll
        for (int r = 0; r < 5; ++r)
            #pragma unroll
            for (int c = 0; c < 5; ++c) acc2[r][c] = 0ull;

        const float* Ri = Ssm + (5 * ti) * SR;
        const float* Rj = Ssm + (5 * tj) * SR;
        #pragma unroll 1
        for (int it = 0; it < 10; ++it) {       // 10 * 64 = 640 (2 floats/lane)
            int off = 2 * lane + 64 * it;
            unsigned long long av[5], bv[5];
            #pragma unroll
            for (int r = 0; r < 5; ++r)
                av[r] = *(const unsigned long long*)(Ri + r * SR + off);
            #pragma unroll
            for (int c = 0; c < 5; ++c)
                bv[c] = *(const unsigned long long*)(Rj + c * SR + off);
            #pragma unroll
            for (int r = 0; r < 5; ++r)
                #pragma unroll
                for (int c = 0; c < 5; ++c)
                    fma_f32x2(acc2[r][c], av[r], bv[c]);
        }
        // collapse pack halves + warp reduce
        #pragma unroll
        for (int r = 0; r < 5; ++r)
            #pragma unroll
            for (int c = 0; c < 5; ++c) {
                float2 p = *reinterpret_cast<float2*>(&acc2[r][c]);
                float v = p.x + p.y;
                v += __shfl_down_sync(0xffffffffu, v, 16);
                v += __shfl_down_sync(0xffffffffu, v, 8);
                v += __shfl_down_sync(0xffffffffu, v, 4);
                v += __shfl_down_sync(0xffffffffu, v, 2);
                v += __shfl_down_sync(0xffffffffu, v, 1);
                if (lane == 0) {
                    int i = 5 * ti + r, j = 5 * tj + c;
                    float g = v + (i == j ? RIDGE : 0.f);
                    A[i * ACOLS + j] = g;
                    A[j * ACOLS + i] = g;
                }
            }
    }
    // one-hot Y into columns 25..29
    if (t < 125) {
        int i = t / 5, w = t - i * 5;
        int base = b * NS + i;
        int lab = lab_i64 ? labels_raw[2 * base] : labels_raw[base];
        A[i * ACOLS + 25 + w] = (lab == w) ? 1.f : 0.f;
    }
    __syncthreads();

    // ---- solve: block-parallel Gauss-Jordan (250 threads, 3 cols each) ----
    {
        const int gi = t % 25;
        const int gj = t / 25;            // 0..9 active
        const bool act = (t < 250);
        for (int k = 0; k < NS; ++k) {
            float f = 0.f, pk0 = 0.f, pk1 = 0.f, pk2 = 0.f;
            if (act) {
                f   = A[gi * ACOLS + k] / A[k * ACOLS + k];
                pk0 = A[k * ACOLS + gj];
                pk1 = A[k * ACOLS + gj + 10];
                pk2 = A[k * ACOLS + gj + 20];
            }
            __syncthreads();
            if (act && gi != k) {
                A[gi * ACOLS + gj]      -= f * pk0;
                A[gi * ACOLS + gj + 10] -= f * pk1;
                A[gi * ACOLS + gj + 20] -= f * pk2;
            }
            __syncthreads();
        }
    }
    if (t < 125) {
        int i = t / 5, w = t - i * 5;
        SOL[i * 8 + w] = A[i * ACOLS + 25 + w] / A[i * ACOLS + i];
    }
    __syncthreads();

    // ---- W[w][d] = sum_s S[s][d] * sol[s][w]  -> global scratch ----
    {
        float* Wb = g_W + (size_t)b * NWAY * DQ;
        int d0 = t, d1 = t + 256, d2 = t + 512;
        bool h2 = (d2 < DQ);
        float a0[5], a1[5], a2[5];
        #pragma unroll
        for (int w = 0; w < 5; ++w) { a0[w] = 0.f; a1[w] = 0.f; a2[w] = 0.f; }
        for (int s = 0; s < NS; ++s) {
            float s0 = Ssm[s * SR + d0];
            float s1 = Ssm[s * SR + d1];
            float s2 = h2 ? Ssm[s * SR + d2] : 0.f;
            #pragma unroll
            for (int w = 0; w < 5; ++w) {
                float sv = SOL[s * 8 + w];
                a0[w] = fmaf(s0, sv, a0[w]);
                a1[w] = fmaf(s1, sv, a1[w]);
                a2[w] = fmaf(s2, sv, a2[w]);
            }
        }
        #pragma unroll
        for (int w = 0; w < 5; ++w) {
            Wb[w * DQ + d0] = a0[w];
            Wb[w * DQ + d1] = a1[w];
            if (h2) Wb[w * DQ + d2] = a2[w];
        }
    }
}

// ---------------- Kernel B: logits = Q @ W (unchanged: 71% DRAM SOL) ----------------
#define B_OFF_WT  0
#define B_OFF_LOG 3200
#define B_SMEM_FLOATS 3576

__global__ __launch_bounds__(256, 3)
void r2d2_logits(const float* __restrict__ query,
                 float* __restrict__ out)
{
    extern __shared__ float sm[];
    float* WT  = sm + B_OFF_WT;
    float* LOG = sm + B_OFF_LOG;

    const int b = blockIdx.x;
    const int t = threadIdx.x;
    const int warp = t >> 5, lane = t & 31;

    {
        const float4* Wg4 = (const float4*)(g_W + (size_t)b * NWAY * DQ);
        float4* Wt4 = (float4*)WT;
        for (int idx = t; idx < NWAY * DQ / 4; idx += 256)
            Wt4[idx] = Wg4[idx];
    }
    __syncthreads();

    const float4* Qb = (const float4*)(query + (size_t)b * NQ * DQ);
    for (int g = warp; g < 15; g += 8) {
        int r0 = g * 5;
        float acc[5][5];
        #pragma unroll
        for (int r = 0; r < 5; ++r)
            #pragma unroll
            for (int w = 0; w < 5; ++w) acc[r][w] = 0.f;

        #pragma unroll
        for (int it = 0; it < 5; ++it) {
            int d4 = lane + it * 32;
            float4 qv[5], wv[5];
            #pragma unroll
            for (int r = 0; r < 5; ++r) qv[r] = __ldcs(&Qb[(r0 + r) * 160 + d4]);
            #pragma unroll
            for (int w = 0; w < 5; ++w)
                wv[w] = *(const float4*)&WT[w * WS + d4 * 4];
            #pragma unroll
            for (int r = 0; r < 5; ++r)
                #pragma unroll
                for (int w = 0; w < 5; ++w) {
                    acc[r][w] = fmaf(qv[r].x, wv[w].x, acc[r][w]);
                    acc[r][w] = fmaf(qv[r].y, wv[w].y, acc[r][w]);
                    acc[r][w] = fmaf(qv[r].z, wv[w].z, acc[r][w]);
                    acc[r][w] = fmaf(qv[r].w, wv[w].w, acc[r][w]);
                }
        }
        #pragma unroll
        for (int r = 0; r < 5; ++r)
            #pragma unroll
            for (int w = 0; w < 5; ++w) {
                float v = acc[r][w];
                v += __shfl_xor_sync(0xffffffffu, v, 16);
                v += __shfl_xor_sync(0xffffffffu, v, 8);
                v += __shfl_xor_sync(0xffffffffu, v, 4);
                v += __shfl_xor_sync(0xffffffffu, v, 2);
                v += __shfl_xor_sync(0xffffffffu, v, 1);
                acc[r][w] = v;
            }
        if (lane == 0) {
            #pragma unroll
            for (int r = 0; r < 5; ++r)
                #pragma unroll
                for (int w = 0; w < 5; ++w)
                    LOG[(r0 + r) * 5 + w] = acc[r][w];
        }
    }
    __syncthreads();

    for (int idx = t; idx < NQ * NWAY; idx += 256)
        out[(size_t)b * (NQ * NWAY) + idx] = LOG[idx];
}

extern "C" void kernel_launch(void* const* d_in, const int* in_sizes, int n_in,
                              void* d_out, int out_size)
{
    const float* query   = (const float*)d_in[0];
    const float* support = (const float*)d_in[1];
    const int* labels    = (const int*)d_in[2];
    float* out = (float*)d_out;

    int tasks = in_sizes[1] / (NS * DQ);
    if (tasks > TASKS_MAX) tasks = TASKS_MAX;

    size_t smemA = (size_t)A_SMEM_FLOATS * sizeof(float);
    cudaFuncSetAttribute(r2d2_prep,
                         cudaFuncAttributeMaxDynamicSharedMemorySize, (int)smemA);
    size_t smemB = (size_t)B_SMEM_FLOATS * sizeof(float);

    r2d2_prep<<<tasks, 256, smemA>>>(support, labels);
    r2d2_logits<<<tasks, 256, smemB>>>(query, out);
}